// round 2
// baseline (speedup 1.0000x reference)
#include <cuda_runtime.h>
#include <math.h>

#define B 8
#define T 2048
#define H 1024
#define V 256
#define GRID 128
#define NTHR 256
#define UPC 8            // hidden units per CTA
#define HPAD 1028        // padded h row (floats) to dodge bank conflicts

#define LSTM_SMEM_FLOATS (32768 + B*HPAD + 64)
#define LSTM_SMEM_BYTES  (LSTM_SMEM_FLOATS * 4)

#define PPC 16           // positions per CTA in loss kernel
#define LOSS_GRID ((B*T)/PPC)   // 1024
#define LOSS_SMEM_FLOATS (PPC*1024 + PPC*256 + PPC)
#define LOSS_SMEM_BYTES  (LOSS_SMEM_FLOATS * 4)

// ---------------- device scratch (static; no allocation) ----------------
__device__ float    g_hs[B * T * H];        // all hidden states, [b][t][j], 64 MiB
__device__ float    g_hbuf[2][B][H];        // double-buffered h for the recurrence
__device__ unsigned g_count;                // grid barrier counter (monotonic per launch)
__device__ float    g_partials[LOSS_GRID];  // per-CTA NLL partial sums

// ---------------- reset: zero barrier counter + h0 ----------------
__global__ void reset_kernel() {
    int tid = threadIdx.x;
    if (tid == 0) g_count = 0u;
    float* h0 = (float*)g_hbuf;        // buffer 0 = first B*H floats
    for (int i = tid; i < B * H; i += blockDim.x) h0[i] = 0.0f;
}

// ---------------- persistent LSTM kernel ----------------
__global__ void __launch_bounds__(NTHR, 1)
lstm_kernel(const int* __restrict__ Xs,
            const float* __restrict__ W_ih,
            const float* __restrict__ W_hh,
            const float* __restrict__ b_ih,
            const float* __restrict__ b_hh)
{
    extern __shared__ float sm[];
    float* W_s    = sm;                    // [UPC][4][1024] = 32768 floats
    float* h_s    = sm + 32768;            // [B][HPAD]
    float* bias_s = sm + 32768 + B * HPAD; // [UPC*4]

    const int tid  = threadIdx.x;
    const int wid  = tid >> 5;             // 0..7 -> unit within CTA
    const int lane = tid & 31;
    const int kq   = lane >> 3;            // 0..3 : K quarter
    const int bb   = lane & 7;             // 0..7 : batch
    const int j0   = blockIdx.x * UPC;
    const int j    = j0 + wid;

    // ---- load this CTA's 32 gate rows of W_hh into SMEM (once) ----
    for (int idx4 = tid; idx4 < 32768 / 4; idx4 += NTHR) {
        int idx = idx4 * 4;
        int u   = idx >> 12;               // unit 0..7
        int q   = (idx >> 10) & 3;         // gate
        int k   = idx & 1023;
        int grow = q * 1024 + j0 + u;
        *(float4*)&W_s[idx] = *(const float4*)&W_hh[grow * 1024 + k];
    }
    if (tid < 32) {
        int u = tid >> 2, q = tid & 3;
        int grow = q * 1024 + j0 + u;
        bias_s[u * 4 + q] = b_ih[grow] + b_hh[grow];
    }
    __syncthreads();

    float c_reg = 0.0f;                    // cell state for (bb, j), lanes 0..7
    const float* Wbase = &W_s[wid * 4096];
    const float* hrow  = &h_s[bb * HPAD];

    for (int t = 0; t < T; ++t) {
        // ---- wait for h_t to be globally visible ----
        if (t > 0) {
            if (tid == 0) {
                unsigned target = (unsigned)t * GRID;
                while (*((volatile unsigned*)&g_count) < target) { __nanosleep(32); }
            }
            __syncthreads();
            __threadfence();
        }
        // ---- stage h_t into SMEM (bypass L1: other SMs wrote it) ----
        {
            const float* hb = (const float*)g_hbuf[t & 1];
            for (int idx4 = tid; idx4 < (B * H) / 4; idx4 += NTHR) {
                int idx = idx4 * 4;
                int b2  = idx >> 10;
                int k   = idx & 1023;
                float4 v = __ldcg((const float4*)&hb[idx]);
                *(float4*)&h_s[b2 * HPAD + k] = v;
            }
        }
        __syncthreads();

        // ---- gate dot products: acc[q] over this lane's K quarter ----
        float accA0 = 0.f, accA1 = 0.f, accA2 = 0.f, accA3 = 0.f;
        float accB0 = 0.f, accB1 = 0.f, accB2 = 0.f, accB3 = 0.f;
        #pragma unroll 4
        for (int i = 0; i < 32; ++i) {
            int kb = i * 32 + kq * 8;
            float4 ha = *(const float4*)&hrow[kb];
            float4 hc = *(const float4*)&hrow[kb + 4];
            {
                float4 wa = *(const float4*)&Wbase[0 * 1024 + kb];
                float4 wb = *(const float4*)&Wbase[0 * 1024 + kb + 4];
                accA0 = fmaf(wa.x, ha.x, accA0); accA0 = fmaf(wa.y, ha.y, accA0);
                accA0 = fmaf(wa.z, ha.z, accA0); accA0 = fmaf(wa.w, ha.w, accA0);
                accB0 = fmaf(wb.x, hc.x, accB0); accB0 = fmaf(wb.y, hc.y, accB0);
                accB0 = fmaf(wb.z, hc.z, accB0); accB0 = fmaf(wb.w, hc.w, accB0);
            }
            {
                float4 wa = *(const float4*)&Wbase[1 * 1024 + kb];
                float4 wb = *(const float4*)&Wbase[1 * 1024 + kb + 4];
                accA1 = fmaf(wa.x, ha.x, accA1); accA1 = fmaf(wa.y, ha.y, accA1);
                accA1 = fmaf(wa.z, ha.z, accA1); accA1 = fmaf(wa.w, ha.w, accA1);
                accB1 = fmaf(wb.x, hc.x, accB1); accB1 = fmaf(wb.y, hc.y, accB1);
                accB1 = fmaf(wb.z, hc.z, accB1); accB1 = fmaf(wb.w, hc.w, accB1);
            }
            {
                float4 wa = *(const float4*)&Wbase[2 * 1024 + kb];
                float4 wb = *(const float4*)&Wbase[2 * 1024 + kb + 4];
                accA2 = fmaf(wa.x, ha.x, accA2); accA2 = fmaf(wa.y, ha.y, accA2);
                accA2 = fmaf(wa.z, ha.z, accA2); accA2 = fmaf(wa.w, ha.w, accA2);
                accB2 = fmaf(wb.x, hc.x, accB2); accB2 = fmaf(wb.y, hc.y, accB2);
                accB2 = fmaf(wb.z, hc.z, accB2); accB2 = fmaf(wb.w, hc.w, accB2);
            }
            {
                float4 wa = *(const float4*)&Wbase[3 * 1024 + kb];
                float4 wb = *(const float4*)&Wbase[3 * 1024 + kb + 4];
                accA3 = fmaf(wa.x, ha.x, accA3); accA3 = fmaf(wa.y, ha.y, accA3);
                accA3 = fmaf(wa.z, ha.z, accA3); accA3 = fmaf(wa.w, ha.w, accA3);
                accB3 = fmaf(wb.x, hc.x, accB3); accB3 = fmaf(wb.y, hc.y, accB3);
                accB3 = fmaf(wb.z, hc.z, accB3); accB3 = fmaf(wb.w, hc.w, accB3);
            }
        }
        float s0 = accA0 + accB0;
        float s1 = accA1 + accB1;
        float s2 = accA2 + accB2;
        float s3 = accA3 + accB3;
        // reduce over the 4 K-quarters (lanes differing in bits 3..4)
        s0 += __shfl_xor_sync(0xffffffffu, s0, 8);
        s0 += __shfl_xor_sync(0xffffffffu, s0, 16);
        s1 += __shfl_xor_sync(0xffffffffu, s1, 8);
        s1 += __shfl_xor_sync(0xffffffffu, s1, 16);
        s2 += __shfl_xor_sync(0xffffffffu, s2, 8);
        s2 += __shfl_xor_sync(0xffffffffu, s2, 16);
        s3 += __shfl_xor_sync(0xffffffffu, s3, 8);
        s3 += __shfl_xor_sync(0xffffffffu, s3, 16);

        if (kq == 0) {
            int x = __ldg(&Xs[bb * T + t]);
            float g0 = s0 + __ldg(&W_ih[(0 * 1024 + j) * V + x]) + bias_s[wid * 4 + 0];
            float g1 = s1 + __ldg(&W_ih[(1 * 1024 + j) * V + x]) + bias_s[wid * 4 + 1];
            float g2 = s2 + __ldg(&W_ih[(2 * 1024 + j) * V + x]) + bias_s[wid * 4 + 2];
            float g3 = s3 + __ldg(&W_ih[(3 * 1024 + j) * V + x]) + bias_s[wid * 4 + 3];
            float ig = 1.0f / (1.0f + __expf(-g0));
            float fg = 1.0f / (1.0f + __expf(-g1));
            float gg = tanhf(g2);
            float og = 1.0f / (1.0f + __expf(-g3));
            c_reg = fg * c_reg + ig * gg;
            float hnew = og * tanhf(c_reg);
            g_hbuf[(t + 1) & 1][bb][j] = hnew;
            g_hs[(bb * T + t) * H + j] = hnew;
        }
        __threadfence();
        __syncthreads();
        if (tid == 0) atomicAdd(&g_count, 1u);
    }
}

// ---------------- loss kernel: logits + logsumexp + NLL partials ----------------
__global__ void __launch_bounds__(256, 1)
loss_kernel(const int* __restrict__ ys,
            const float* __restrict__ W1,
            const float* __restrict__ b1)
{
    extern __shared__ float sm[];
    float* h_sm     = sm;                       // [PPC][1024]
    float* logit_sm = sm + PPC * 1024;          // [PPC][256]
    float* red      = logit_sm + PPC * 256;     // [PPC]

    const int tid  = threadIdx.x;
    const int pos0 = blockIdx.x * PPC;

    for (int idx4 = tid; idx4 < PPC * 1024 / 4; idx4 += 256) {
        int idx = idx4 * 4;
        *(float4*)&h_sm[idx] = *(const float4*)&g_hs[pos0 * 1024 + idx];
    }
    __syncthreads();

    float acc[PPC];
    #pragma unroll
    for (int p = 0; p < PPC; ++p) acc[p] = 0.0f;

    const float* wrow = &W1[tid * 1024];
    for (int k = 0; k < 1024; k += 4) {
        float4 w = __ldg((const float4*)&wrow[k]);
        #pragma unroll
        for (int p = 0; p < PPC; ++p) {
            float4 hv = *(const float4*)&h_sm[p * 1024 + k];  // broadcast
            acc[p] = fmaf(w.x, hv.x, acc[p]);
            acc[p] = fmaf(w.y, hv.y, acc[p]);
            acc[p] = fmaf(w.z, hv.z, acc[p]);
            acc[p] = fmaf(w.w, hv.w, acc[p]);
        }
    }
    float bv = b1[tid];
    #pragma unroll
    for (int p = 0; p < PPC; ++p) logit_sm[p * 256 + tid] = acc[p] + bv;
    __syncthreads();

    const int wid = tid >> 5, lane = tid & 31;
    #pragma unroll
    for (int pp = 0; pp < 2; ++pp) {
        int p = wid * 2 + pp;
        const float* L = &logit_sm[p * 256];
        float v[8];
        #pragma unroll
        for (int i = 0; i < 8; ++i) v[i] = L[lane + 32 * i];
        float m = v[0];
        #pragma unroll
        for (int i = 1; i < 8; ++i) m = fmaxf(m, v[i]);
        for (int off = 16; off; off >>= 1)
            m = fmaxf(m, __shfl_xor_sync(0xffffffffu, m, off));
        float s = 0.0f;
        #pragma unroll
        for (int i = 0; i < 8; ++i) s += expf(v[i] - m);
        for (int off = 16; off; off >>= 1)
            s += __shfl_xor_sync(0xffffffffu, s, off);
        if (lane == 0) {
            int pos = pos0 + p;
            int y   = __ldg(&ys[pos]);           // ys is [B][T], pos = b*T+t
            float lse = m + logf(s);
            red[p] = lse - L[y];
        }
    }
    __syncthreads();
    if (tid == 0) {
        float ssum = 0.0f;
        #pragma unroll
        for (int p = 0; p < PPC; ++p) ssum += red[p];
        g_partials[blockIdx.x] = ssum;
    }
}

// ---------------- final reduction -> mean NLL ----------------
__global__ void final_kernel(float* __restrict__ out) {
    __shared__ float red[256];
    int tid = threadIdx.x;
    float s = 0.0f;
    for (int i = tid; i < LOSS_GRID; i += 256) s += g_partials[i];
    red[tid] = s;
    __syncthreads();
    for (int off = 128; off; off >>= 1) {
        if (tid < off) red[tid] += red[tid + off];
        __syncthreads();
    }
    if (tid == 0) out[0] = red[0] / (float)(B * T);
}

// ---------------- launch ----------------
extern "C" void kernel_launch(void* const* d_in, const int* in_sizes, int n_in,
                              void* d_out, int out_size)
{
    const int*   Xs   = (const int*)d_in[0];
    const int*   ys   = (const int*)d_in[1];
    /* d_in[2] = predict (always 0 here) */
    const float* W_ih = (const float*)d_in[3];
    const float* W_hh = (const float*)d_in[4];
    const float* b_ih = (const float*)d_in[5];
    const float* b_hh = (const float*)d_in[6];
    const float* W1   = (const float*)d_in[7];
    const float* b1   = (const float*)d_in[8];
    float* out = (float*)d_out;

    cudaFuncSetAttribute(lstm_kernel, cudaFuncAttributeMaxDynamicSharedMemorySize,
                         LSTM_SMEM_BYTES);
    cudaFuncSetAttribute(loss_kernel, cudaFuncAttributeMaxDynamicSharedMemorySize,
                         LOSS_SMEM_BYTES);

    reset_kernel<<<1, 256>>>();
    lstm_kernel<<<GRID, NTHR, LSTM_SMEM_BYTES>>>(Xs, W_ih, W_hh, b_ih, b_hh);
    loss_kernel<<<LOSS_GRID, 256, LOSS_SMEM_BYTES>>>(ys, W1, b1);
    final_kernel<<<1, 256>>>(out);
    (void)in_sizes; (void)n_in; (void)out_size;
}

// round 3
// speedup vs baseline: 1.5053x; 1.5053x over previous
#include <cuda_runtime.h>
#include <math.h>

#define B 8
#define T 2048
#define H 1024
#define V 256
#define GRID 128
#define NTHR 256
#define UPC 8            // hidden units per CTA (1 per warp)

typedef unsigned long long ull;

#define PPC 16                   // positions per CTA in loss kernel
#define LOSS_GRID ((B*T)/PPC)    // 1024
#define LOSS_SMEM_FLOATS (PPC*1024 + PPC*256 + PPC)
#define LOSS_SMEM_BYTES  (LOSS_SMEM_FLOATS * 4)

// ---------------- device scratch (static; no allocation) ----------------
__device__ float    g_hs[B * T * H];        // hidden states, layout [t][b][j]
__device__ float    g_hbuf[2][B][H];        // double-buffered h for the recurrence
__device__ unsigned g_count;                // grid barrier counter
__device__ float    g_partials[LOSS_GRID];  // per-CTA NLL partial sums

// ---------------- packed f32x2 helpers ----------------
__device__ __forceinline__ ull fma2(ull a, ull b, ull c) {
    ull d;
    asm("fma.rn.f32x2 %0, %1, %2, %3;" : "=l"(d) : "l"(a), "l"(b), "l"(c));
    return d;
}
__device__ __forceinline__ float2 unpk(ull v) {
    float2 r;
    asm("mov.b64 {%0, %1}, %2;" : "=f"(r.x), "=f"(r.y) : "l"(v));
    return r;
}

// ---------------- reset: zero barrier counter + h0 ----------------
__global__ void reset_kernel() {
    int tid = threadIdx.x;
    if (tid == 0) g_count = 0u;
    float* h0 = (float*)g_hbuf;        // buffer 0 = first B*H floats
    for (int i = tid; i < B * H; i += blockDim.x) h0[i] = 0.0f;
}

// ---------------- persistent LSTM kernel (weights in registers) ----------------
__global__ void __launch_bounds__(NTHR, 1)
lstm_kernel(const int* __restrict__ Xs,
            const float* __restrict__ W_ih,
            const float* __restrict__ W_hh,
            const float* __restrict__ b_ih,
            const float* __restrict__ b_hh)
{
    // h tile: [B][32 lanes][8 float4], XOR-swizzled on the low 3 f4-bits
    __shared__ float4 h4s[B * 256];         // 32 KB
    __shared__ float  scr[UPC][32];         // gate-scatter scratch, 1 KB

    const int tid  = threadIdx.x;
    const int wid  = tid >> 5;              // unit within CTA
    const int lane = tid & 31;              // K-chunk: [lane*32, lane*32+32)
    const int j0   = blockIdx.x * UPC;
    const int j    = j0 + wid;

    // ---- load this thread's 128 weight floats into registers (once) ----
    ull w2[4][16];
    #pragma unroll
    for (int g = 0; g < 4; ++g) {
        const ulonglong2* src =
            (const ulonglong2*)&W_hh[(g * H + j) * H + lane * 32];
        #pragma unroll
        for (int i = 0; i < 8; ++i) {
            ulonglong2 tt = src[i];
            w2[g][2*i]   = tt.x;
            w2[g][2*i+1] = tt.y;
        }
    }
    float bias0 = b_ih[0*H + j] + b_hh[0*H + j];
    float bias1 = b_ih[1*H + j] + b_hh[1*H + j];
    float bias2 = b_ih[2*H + j] + b_hh[2*H + j];
    float bias3 = b_ih[3*H + j] + b_hh[3*H + j];

    float c_reg = 0.0f;                     // cell state for (b=lane, j), lanes 0..7

    for (int t = 0; t < T; ++t) {
        // ---- wait for h_t to be globally visible ----
        if (t > 0) {
            if (tid == 0) {
                unsigned target = (unsigned)t * GRID;
                while (*((volatile unsigned*)&g_count) < target) { __nanosleep(32); }
            }
            __syncthreads();
        }
        // ---- stage h_t into swizzled SMEM (bypass L1) ----
        {
            const float4* hb = (const float4*)g_hbuf[t & 1];
            #pragma unroll
            for (int f = tid; f < B * 256; f += NTHR) {
                int b2 = f >> 8;
                int l2 = (f >> 3) & 31;
                int i2 = f & 7;
                float4 vv = __ldcg(hb + f);
                h4s[b2 * 256 + l2 * 8 + ((i2 + l2) & 7)] = vv;
            }
        }
        __syncthreads();

        // ---- gate partials: 512 FFMA2 per thread ----
        float v[32];
        const ulonglong2* hbase = (const ulonglong2*)h4s + lane * 8;
        #pragma unroll
        for (int b = 0; b < B; ++b) {
            ull a0 = 0ull, a1 = 0ull, a2 = 0ull, a3 = 0ull;
            const ulonglong2* hrow = hbase + b * 256;
            #pragma unroll
            for (int i = 0; i < 8; ++i) {
                ulonglong2 hv = hrow[(i + lane) & 7];
                a0 = fma2(w2[0][2*i],   hv.x, a0);
                a1 = fma2(w2[1][2*i],   hv.x, a1);
                a2 = fma2(w2[2][2*i],   hv.x, a2);
                a3 = fma2(w2[3][2*i],   hv.x, a3);
                a0 = fma2(w2[0][2*i+1], hv.y, a0);
                a1 = fma2(w2[1][2*i+1], hv.y, a1);
                a2 = fma2(w2[2][2*i+1], hv.y, a2);
                a3 = fma2(w2[3][2*i+1], hv.y, a3);
            }
            float2 f0 = unpk(a0), f1 = unpk(a1), f2 = unpk(a2), f3 = unpk(a3);
            v[0*8 + b] = f0.x + f0.y;
            v[1*8 + b] = f1.x + f1.y;
            v[2*8 + b] = f2.x + f2.y;
            v[3*8 + b] = f3.x + f3.y;
        }

        // ---- multi-value butterfly: reduce 32 outputs across 32 lanes ----
        #pragma unroll
        for (int s = 0; s < 5; ++s) {
            const int m   = 1 << s;
            const int cnt = 16 >> s;
            const bool up = (lane & m) != 0;
            #pragma unroll
            for (int i = 0; i < cnt; ++i) {
                float send = up ? v[i] : v[i + cnt];
                float recv = __shfl_xor_sync(0xffffffffu, send, m);
                float keep = up ? v[i + cnt] : v[i];
                v[i] = keep + recv;
            }
        }
        // lane holds output o = bitrev5(lane): o = g*8 + b
        {
            int o = (int)(__brev((unsigned)lane) >> 27);
            scr[wid][o] = v[0];
        }
        __syncwarp();

        if (lane < 8) {
            const int b = lane;
            int x = __ldg(&Xs[b * T + t]);
            float g0 = scr[wid][0*8 + b] + __ldg(&W_ih[(0*H + j) * V + x]) + bias0;
            float g1 = scr[wid][1*8 + b] + __ldg(&W_ih[(1*H + j) * V + x]) + bias1;
            float g2 = scr[wid][2*8 + b] + __ldg(&W_ih[(2*H + j) * V + x]) + bias2;
            float g3 = scr[wid][3*8 + b] + __ldg(&W_ih[(3*H + j) * V + x]) + bias3;
            float ig = 1.0f / (1.0f + __expf(-g0));
            float fg = 1.0f / (1.0f + __expf(-g1));
            float gg = tanhf(g2);
            float og = 1.0f / (1.0f + __expf(-g3));
            c_reg = fg * c_reg + ig * gg;
            float hnew = og * tanhf(c_reg);
            g_hbuf[(t + 1) & 1][b][j] = hnew;
            g_hs[(t * B + b) * H + j] = hnew;      // layout [t][b][j]
        }
        __threadfence();
        __syncthreads();
        if (tid == 0) atomicAdd(&g_count, 1u);
    }
}

// ---------------- loss kernel: logits + logsumexp + NLL partials ----------------
__global__ void __launch_bounds__(256, 1)
loss_kernel(const int* __restrict__ ys,
            const float* __restrict__ W1,
            const float* __restrict__ b1)
{
    extern __shared__ float sm[];
    float* h_sm     = sm;                       // [PPC][1024]
    float* logit_sm = sm + PPC * 1024;          // [PPC][256]
    float* red      = logit_sm + PPC * 256;     // [PPC]

    const int tid  = threadIdx.x;
    const int pos0 = blockIdx.x * PPC;          // pos = t*B + b

    for (int idx4 = tid; idx4 < PPC * 1024 / 4; idx4 += 256) {
        int idx = idx4 * 4;
        *(float4*)&h_sm[idx] = *(const float4*)&g_hs[pos0 * 1024 + idx];
    }
    __syncthreads();

    ull acc2[PPC];
    #pragma unroll
    for (int p = 0; p < PPC; ++p) acc2[p] = 0ull;

    const ulonglong2* wrow = (const ulonglong2*)&W1[tid * 1024];
    for (int k4 = 0; k4 < 256; ++k4) {
        ulonglong2 w = __ldg(wrow + k4);
        #pragma unroll
        for (int p = 0; p < PPC; ++p) {
            ulonglong2 hv = *(const ulonglong2*)&h_sm[p * 1024 + k4 * 4];
            acc2[p] = fma2(w.x, hv.x, acc2[p]);
            acc2[p] = fma2(w.y, hv.y, acc2[p]);
        }
    }
    float bv = b1[tid];
    #pragma unroll
    for (int p = 0; p < PPC; ++p) {
        float2 f = unpk(acc2[p]);
        logit_sm[p * 256 + tid] = f.x + f.y + bv;
    }
    __syncthreads();

    const int wid = tid >> 5, lane = tid & 31;
    #pragma unroll
    for (int pp = 0; pp < 2; ++pp) {
        int p = wid * 2 + pp;
        const float* L = &logit_sm[p * 256];
        float vv[8];
        #pragma unroll
        for (int i = 0; i < 8; ++i) vv[i] = L[lane + 32 * i];
        float m = vv[0];
        #pragma unroll
        for (int i = 1; i < 8; ++i) m = fmaxf(m, vv[i]);
        for (int off = 16; off; off >>= 1)
            m = fmaxf(m, __shfl_xor_sync(0xffffffffu, m, off));
        float s = 0.0f;
        #pragma unroll
        for (int i = 0; i < 8; ++i) s += expf(vv[i] - m);
        for (int off = 16; off; off >>= 1)
            s += __shfl_xor_sync(0xffffffffu, s, off);
        if (lane == 0) {
            int pos = pos0 + p;                  // pos = t*B + b
            int b   = pos & 7;
            int t   = pos >> 3;
            int y   = __ldg(&ys[b * T + t]);
            float lse = m + logf(s);
            red[p] = lse - L[y];
        }
    }
    __syncthreads();
    if (tid == 0) {
        float ssum = 0.0f;
        #pragma unroll
        for (int p = 0; p < PPC; ++p) ssum += red[p];
        g_partials[blockIdx.x] = ssum;
    }
}

// ---------------- final reduction -> mean NLL ----------------
__global__ void final_kernel(float* __restrict__ out) {
    __shared__ float red[256];
    int tid = threadIdx.x;
    float s = 0.0f;
    for (int i = tid; i < LOSS_GRID; i += 256) s += g_partials[i];
    red[tid] = s;
    __syncthreads();
    for (int off = 128; off; off >>= 1) {
        if (tid < off) red[tid] += red[tid + off];
        __syncthreads();
    }
    if (tid == 0) out[0] = red[0] / (float)(B * T);
}

// ---------------- launch ----------------
extern "C" void kernel_launch(void* const* d_in, const int* in_sizes, int n_in,
                              void* d_out, int out_size)
{
    const int*   Xs   = (const int*)d_in[0];
    const int*   ys   = (const int*)d_in[1];
    /* d_in[2] = predict (always 0 here) */
    const float* W_ih = (const float*)d_in[3];
    const float* W_hh = (const float*)d_in[4];
    const float* b_ih = (const float*)d_in[5];
    const float* b_hh = (const float*)d_in[6];
    const float* W1   = (const float*)d_in[7];
    const float* b1   = (const float*)d_in[8];
    float* out = (float*)d_out;

    cudaFuncSetAttribute(loss_kernel, cudaFuncAttributeMaxDynamicSharedMemorySize,
                         LOSS_SMEM_BYTES);

    reset_kernel<<<1, 256>>>();
    lstm_kernel<<<GRID, NTHR>>>(Xs, W_ih, W_hh, b_ih, b_hh);
    loss_kernel<<<LOSS_GRID, 256, LOSS_SMEM_BYTES>>>(ys, W1, b1);
    final_kernel<<<1, 256>>>(out);
    (void)in_sizes; (void)n_in; (void)out_size;
}